// round 6
// baseline (speedup 1.0000x reference)
#include <cuda_runtime.h>

// CorrAttentionBias: out[b,h,i,j] = attn + alpha*edge + beta*cs_i*cs_j, masked to NEG.
// B=2, H=16, L=2048. Pure HBM streaming; masked rows skip the attn read.
// One row per block, one 32-byte chunk per thread (256 thr x 8 floats = 2048).
// alignas(32) aggregates let ptxas emit 256-bit LDG/STG on sm_103a.
// Mask dtype is int32 (proven on this dataset).

#define ALPHA 0.5f
#define BETA  0.1f
#define NEGV  -100000.0f

namespace {
constexpr int B = 2;
constexpr int H = 16;
constexpr int L = 2048;
constexpr int THREADS = 256;   // 256 * 8 floats = 2048 = one full row
}

struct alignas(32) F8 { float4 lo, hi; };
struct alignas(32) I8 { int4 lo, hi; };

__global__ __launch_bounds__(THREADS) void corr_bias_kernel(
    const float* __restrict__ attn,
    const float* __restrict__ c_local,
    const float* __restrict__ c_sink,
    const int* __restrict__ mask,     // int32 per element
    float* __restrict__ out)
{
    const unsigned r = blockIdx.x;            // r = (b*H + h)*L + i
    const int i = r & (L - 1);
    const int b = r >> 15;                    // H*L = 32768
    const long long base = (long long)r * L;
    const int t = threadIdx.x;

    F8* __restrict__ o8 = reinterpret_cast<F8*>(out + base);

    // Fully-masked row: write-only fast path (saves ~50% of attn reads).
    if (mask[b * L + i]) {
        const float4 neg = make_float4(NEGV, NEGV, NEGV, NEGV);
        F8 w; w.lo = neg; w.hi = neg;
        o8[t] = w;
        return;
    }

    const F8* __restrict__ a8  = reinterpret_cast<const F8*>(attn + base);
    const F8* __restrict__ cs8 = reinterpret_cast<const F8*>(c_sink + b * L);
    const I8* __restrict__ m8  = reinterpret_cast<const I8*>(mask + b * L);

    const float csi = BETA * c_sink[b * L + i];

    // Neighbor bias values, matching the reference's overwrite semantics:
    //   j = i+1 : alpha * c_local[b, i+1]                     (i <= L-2)
    //   j = i-1 : alpha * c_local[b, i-1]  if 2 <= i <= L-2
    //             alpha * c_local[b, i]    if i == 1 or i == L-1
    float nl = 0.f, nr = 0.f;
    if (i >= 1) {
        nl = (i >= 2 && i <= L - 2) ? ALPHA * c_local[b * L + i - 1]
                                    : ALPHA * c_local[b * L + i];
    }
    if (i <= L - 2) {
        nr = ALPHA * c_local[b * L + i + 1];
    }

    const int j0 = t * 8;                     // first column of this chunk

    const F8 a  = a8[t];
    const F8 cs = cs8[t];
    const I8 m  = m8[t];

    F8 o;
    o.lo.x = fmaf(csi, cs.lo.x, a.lo.x);
    o.lo.y = fmaf(csi, cs.lo.y, a.lo.y);
    o.lo.z = fmaf(csi, cs.lo.z, a.lo.z);
    o.lo.w = fmaf(csi, cs.lo.w, a.lo.w);
    o.hi.x = fmaf(csi, cs.hi.x, a.hi.x);
    o.hi.y = fmaf(csi, cs.hi.y, a.hi.y);
    o.hi.z = fmaf(csi, cs.hi.z, a.hi.z);
    o.hi.w = fmaf(csi, cs.hi.w, a.hi.w);

    // Neighbor diagonals: at most two lanes in the whole row hit; cheap
    // uniform reject for chunks that can't contain i-1 or i+1.
    if (j0 <= i + 1 && i - 1 < j0 + 8) {
        float* oe = reinterpret_cast<float*>(&o);
        #pragma unroll
        for (int e = 0; e < 8; e++) {
            const int j = j0 + e;
            if (j == i - 1) oe[e] += nl;
            else if (j == i + 1) oe[e] += nr;
        }
    }

    if (m.lo.x) o.lo.x = NEGV;
    if (m.lo.y) o.lo.y = NEGV;
    if (m.lo.z) o.lo.z = NEGV;
    if (m.lo.w) o.lo.w = NEGV;
    if (m.hi.x) o.hi.x = NEGV;
    if (m.hi.y) o.hi.y = NEGV;
    if (m.hi.z) o.hi.z = NEGV;
    if (m.hi.w) o.hi.w = NEGV;

    o8[t] = o;
}

extern "C" void kernel_launch(void* const* d_in, const int* in_sizes, int n_in,
                              void* d_out, int out_size)
{
    const float* attn    = (const float*)d_in[0];
    const float* c_local = (const float*)d_in[1];
    const float* c_sink  = (const float*)d_in[2];
    const int*   mask    = (const int*)d_in[3];
    float*       out     = (float*)d_out;

    const int grid = B * H * L;  // 65536 row-blocks
    corr_bias_kernel<<<grid, THREADS>>>(attn, c_local, c_sink, mask, out);
}